// round 12
// baseline (speedup 1.0000x reference)
#include <cuda_runtime.h>

// SlidingAttnScoreCache — one decode step of a sliding cache at capacity.
// B=8, H=8, S=1024, D=64.
//  0 q_cache (B,H,S,D) f32   1 k_cache   2 v_cache
//  3 attn_score_cache (B,H,S,S) f32
//  4 q (B,H,1,D)  5 k  6 v
//  7 q_t (B,H,1,S)  8 k_t (B,H,S,1)  9 current_seq_len (scalar int)
// Output: concat[q_cache', k_cache', v_cache', attn_score_cache'] f32.

#define Bc 8
#define Hc 8
#define Sc 1024
#define Dc 64
#define D4c (Dc / 4)
#define N_CACHE (Bc * Hc * Sc * Dc)      // 4,194,304 floats per qkv cache
#define N4_CACHE (N_CACHE / 4)           // 1,048,576 float4
#define BH (Bc * Hc)
#define ATTN_ITEMS (BH * Sc / 2)         // 32768 row-pairs
#define QKV_ITEMS (3 * N4_CACHE / 512)   // 6144 chunks of 512 float4
#define TOTAL_ITEMS (ATTN_ITEMS + QKV_ITEMS)
#define GRID_BLKS (152 * 8)              // persistent: 8 blocks per SM

__global__ __launch_bounds__(256, 8)
void sliding_cache_fused(const float4* __restrict__ qc,
                         const float4* __restrict__ kc,
                         const float4* __restrict__ vc,
                         const float*  __restrict__ a_in,
                         const float4* __restrict__ qn,
                         const float4* __restrict__ kn,
                         const float4* __restrict__ vn,
                         const float*  __restrict__ q_t,
                         const float*  __restrict__ k_t,
                         const int*    __restrict__ csl_ptr,
                         float4* __restrict__ out4)
{
    const int tid = threadIdx.x;
    const int t   = tid << 2;

    // loop-invariant state (loaded/derived ONCE per persistent block)
    const int csl    = *csl_ptr;
    const int shiftA = (csl >= Sc - 1) ? 2 : 0;   // attn shift
    const int shiftQ = (csl >= Sc - 1) ? 1 : 0;   // qkv shift
    const int c      = (csl < Sc - 1) ? csl : (Sc - 1);
    float4* attn_out = out4 + (long)(3 * N4_CACHE);

    for (int item = blockIdx.x; item < TOTAL_ITEMS; item += GRID_BLKS) {
        if (item >= QKV_ITEMS) {
            // ------------- attn score cache: rows 2*ab, 2*ab+1 -------------
            int ab   = item - QKV_ITEMS;
            int row0 = ab * 2;
            int s0   = row0 & (Sc - 1);          // even
            int s1   = s0 + 1;
            int bh   = row0 >> 10;

            float4* outp = attn_out + (long)row0 * (Sc / 4) + tid;

            if (shiftA == 2) {
                // c == S-1; s0 even so s0 != c; s1 may be c (last pair of plane).
                int ss0 = s0 + 2; if (ss0 > Sc - 1) ss0 = Sc - 1;
                int ss1 = s1 + 2; if (ss1 > Sc - 1) ss1 = Sc - 1;
                const float* ir0 = a_in + (long)(bh * Sc + ss0) * Sc;
                const float* ir1 = a_in + (long)(bh * Sc + ss1) * Sc;

                float4 v0, v1;
                if (tid != 255) {
                    // out cols t..t+3 <- src cols t+2..t+5 (4 independent LDG.64)
                    float2 a0 = __ldcs(reinterpret_cast<const float2*>(ir0 + t + 2));
                    float2 b0 = __ldcs(reinterpret_cast<const float2*>(ir0 + t + 4));
                    float2 a1 = __ldcs(reinterpret_cast<const float2*>(ir1 + t + 2));
                    float2 b1 = __ldcs(reinterpret_cast<const float2*>(ir1 + t + 4));
                    v0.x = a0.x; v0.y = a0.y; v0.z = b0.x; v0.w = b0.y;
                    v1.x = a1.x; v1.y = a1.y; v1.z = b1.x; v1.w = b1.y;
                } else {
                    // cols 1020..1023: src 1022, 1023, clamp(1024)->1023, col c
                    float2 a0 = __ldcs(reinterpret_cast<const float2*>(ir0 + Sc - 2));
                    float2 a1 = __ldcs(reinterpret_cast<const float2*>(ir1 + Sc - 2));
                    float kt0 = k_t[bh * Sc + s0];
                    float kt1 = k_t[bh * Sc + s1];
                    v0.x = a0.x; v0.y = a0.y; v0.z = a0.y; v0.w = kt0;
                    v1.x = a1.x; v1.y = a1.y; v1.z = a1.y; v1.w = kt1;
                }

                if (s1 == c) {
                    // row c <- q_t; column c (= S-1, tid 255 elem w) <- k_t[c]
                    v1 = __ldcs(reinterpret_cast<const float4*>(q_t + bh * Sc) + tid);
                    if (tid == 255) v1.w = k_t[bh * Sc + c];
                }
                __stcs(outp, v0);
                __stcs(outp + (Sc / 4), v1);
            } else {
                // shift == 0 cold path: plain row copies with patches
                const float* base = a_in + (long)bh * Sc * Sc;
                float4 v0, v1;
                if (s0 == c) {
                    v0 = __ldcs(reinterpret_cast<const float4*>(q_t + bh * Sc) + tid);
                    if (c >= t && c < t + 4)
                        reinterpret_cast<float*>(&v0)[c - t] = k_t[bh * Sc + c];
                } else {
                    v0 = __ldcs(reinterpret_cast<const float4*>(base + (long)s0 * Sc) + tid);
                    if (c >= t && c < t + 4)
                        reinterpret_cast<float*>(&v0)[c - t] = k_t[bh * Sc + s0];
                }
                if (s1 == c) {
                    v1 = __ldcs(reinterpret_cast<const float4*>(q_t + bh * Sc) + tid);
                    if (c >= t && c < t + 4)
                        reinterpret_cast<float*>(&v1)[c - t] = k_t[bh * Sc + c];
                } else {
                    v1 = __ldcs(reinterpret_cast<const float4*>(base + (long)s1 * Sc) + tid);
                    if (c >= t && c < t + 4)
                        reinterpret_cast<float*>(&v1)[c - t] = k_t[bh * Sc + s1];
                }
                __stcs(outp, v0);
                __stcs(outp + (Sc / 4), v1);
            }
        } else {
            // ------------- q/k/v caches: 2 float4 per thread -------------
            int base = item * 512;                   // never spans caches
            int which = base / N4_CACHE;             // 0=q,1=k,2=v
            const float4* in = (which == 0) ? qc : (which == 1) ? kc : vc;
            const float4* nv = (which == 0) ? qn : (which == 1) ? kn : vn;

            int r0 = (base - which * N4_CACHE) + tid;
            int r1 = r0 + 256;

            int d40 = r0 & (D4c - 1), sA = (r0 >> 4) & (Sc - 1), bh0 = r0 >> 14;
            int d41 = r1 & (D4c - 1), sB = (r1 >> 4) & (Sc - 1), bh1 = r1 >> 14;

            int ssA = sA + shiftQ; if (ssA > Sc - 1) ssA = Sc - 1;
            int ssB = sB + shiftQ; if (ssB > Sc - 1) ssB = Sc - 1;

            float4 vA = (sA == c) ? nv[bh0 * D4c + d40]
                                  : __ldcs(in + (long)(bh0 * Sc + ssA) * D4c + d40);
            float4 vB = (sB == c) ? nv[bh1 * D4c + d41]
                                  : __ldcs(in + (long)(bh1 * Sc + ssB) * D4c + d41);

            __stcs(out4 + base + tid, vA);
            __stcs(out4 + base + 256 + tid, vB);
        }
    }
}

extern "C" void kernel_launch(void* const* d_in, const int* in_sizes, int n_in,
                              void* d_out, int out_size)
{
    const float4* qc  = (const float4*)d_in[0];
    const float4* kc  = (const float4*)d_in[1];
    const float4* vc  = (const float4*)d_in[2];
    const float*  ac  = (const float*) d_in[3];
    const float4* qn  = (const float4*)d_in[4];
    const float4* kn  = (const float4*)d_in[5];
    const float4* vn  = (const float4*)d_in[6];
    const float*  qt  = (const float*) d_in[7];
    const float*  kt  = (const float*) d_in[8];
    const int*    csl = (const int*)   d_in[9];

    float4* out4 = (float4*)d_out;

    sliding_cache_fused<<<GRID_BLKS, 256>>>(
        qc, kc, vc, ac, qn, kn, vn, qt, kt, csl, out4);
}

// round 14
// speedup vs baseline: 1.1290x; 1.1290x over previous
#include <cuda_runtime.h>

// SlidingAttnScoreCache — one decode step of a sliding cache at capacity.
// B=8, H=8, S=1024, D=64.
//  0 q_cache (B,H,S,D) f32   1 k_cache   2 v_cache
//  3 attn_score_cache (B,H,S,S) f32
//  4 q (B,H,1,D)  5 k  6 v
//  7 q_t (B,H,1,S)  8 k_t (B,H,S,1)  9 current_seq_len (scalar int)
// Output: concat[q_cache', k_cache', v_cache', attn_score_cache'] f32.
//
// Roofline note: ~637 MB of pure data movement (50/50 R/W). Measured wall
// across 8 structural variants is 82-83% DRAM (~6.6 TB/s) — the mixed
// read/write HBM turnaround ceiling. This kernel sits at that wall.

#define Bc 8
#define Hc 8
#define Sc 1024
#define Dc 64
#define D4c (Dc / 4)
#define N_CACHE (Bc * Hc * Sc * Dc)      // 4,194,304 floats per qkv cache
#define N4_CACHE (N_CACHE / 4)           // 1,048,576 float4
#define BH (Bc * Hc)
#define ATTN_BLOCKS (BH * Sc / 2)        // 32768 blocks, 2 rows each
#define QKV_BLOCKS (3 * N4_CACHE / 512)  // 6144 blocks, 2 float4/thread

// Assemble out[s, 4t..4t+3] = in[ss, 4t+2..4t+5] from the aligned load A_t,
// using shuffles for the cross-thread pair; lane31 uses ext (predicated 8B
// load); tid==255 clamps col 1024 -> 1023 and sets col 1023 (== c) to k_t[s].
__device__ __forceinline__
float4 shift2_assemble(float4 A, float2 ext, int tid, int lane, float ktv)
{
    float nx = __shfl_down_sync(0xffffffffu, A.x, 1);
    float ny = __shfl_down_sync(0xffffffffu, A.y, 1);
    if (lane == 31) { nx = ext.x; ny = ext.y; }
    float4 v;
    v.x = A.z; v.y = A.w; v.z = nx; v.w = ny;
    if (tid == 255) { v.z = A.w; v.w = ktv; }
    return v;
}

__global__ __launch_bounds__(256, 8)
void sliding_cache_fused(const float4* __restrict__ qc,
                         const float4* __restrict__ kc,
                         const float4* __restrict__ vc,
                         const float*  __restrict__ a_in,
                         const float4* __restrict__ qn,
                         const float4* __restrict__ kn,
                         const float4* __restrict__ vn,
                         const float*  __restrict__ q_t,
                         const float*  __restrict__ k_t,
                         const int*    __restrict__ csl_ptr,
                         float4* __restrict__ out4)
{
    int blk  = blockIdx.x;
    int tid  = threadIdx.x;
    int lane = tid & 31;
    int csl  = *csl_ptr;

    if (blk >= QKV_BLOCKS) {
        // ---------------- attn score cache: rows 2*ab, 2*ab+1 ----------------
        int ab   = blk - QKV_BLOCKS;
        int row0 = ab * 2;
        int s0   = row0 & (Sc - 1);          // even
        int s1   = s0 + 1;
        int bh   = row0 >> 10;
        int t    = tid << 2;
        int shift = (csl >= Sc - 1) ? 2 : 0;
        int c     = (csl < Sc - 1) ? csl : (Sc - 1);

        float4* outp = out4 + (long)(3 * N4_CACHE) + (long)row0 * (Sc / 4) + tid;

        if (shift == 2) {
            // c == S-1; s0 even so s0 != c; s1 may be c (last pair of plane).
            int ss0 = s0 + 2; if (ss0 > Sc - 1) ss0 = Sc - 1;
            int ss1 = s1 + 2; if (ss1 > Sc - 1) ss1 = Sc - 1;
            const float* ir0 = a_in + (long)(bh * Sc + ss0) * Sc;
            const float* ir1 = a_in + (long)(bh * Sc + ss1) * Sc;

            // --- issue every load before any consumer ---
            float4 A0 = __ldcs(reinterpret_cast<const float4*>(ir0) + tid);
            float4 A1 = __ldcs(reinterpret_cast<const float4*>(ir1) + tid);
            float2 e0, e1;
            if (lane == 31 && tid != 255) {
                e0 = *reinterpret_cast<const float2*>(ir0 + t + 4);
                e1 = *reinterpret_cast<const float2*>(ir1 + t + 4);
            }
            float kt0 = k_t[bh * Sc + s0];
            float kt1 = k_t[bh * Sc + s1];

            float4 v0 = shift2_assemble(A0, e0, tid, lane, kt0);
            float4 v1 = shift2_assemble(A1, e1, tid, lane, kt1);

            if (s1 == c) {
                // row c <- q_t; column c (= S-1, tid 255 elem w) <- k_t[c]
                v1 = __ldcs(reinterpret_cast<const float4*>(q_t + bh * Sc) + tid);
                if (c >= t && c < t + 4)
                    reinterpret_cast<float*>(&v1)[c - t] = kt1;
            }
            __stcs(outp, v0);
            __stcs(outp + (Sc / 4), v1);
        } else {
            // shift == 0: plain row copies with patches (cold path)
            const float* base = a_in + (long)bh * Sc * Sc;
            float4 v0, v1;
            if (s0 == c) {
                v0 = __ldcs(reinterpret_cast<const float4*>(q_t + bh * Sc) + tid);
                if (c >= t && c < t + 4)
                    reinterpret_cast<float*>(&v0)[c - t] = k_t[bh * Sc + c];
            } else {
                v0 = __ldcs(reinterpret_cast<const float4*>(base + (long)s0 * Sc) + tid);
                if (c >= t && c < t + 4)
                    reinterpret_cast<float*>(&v0)[c - t] = k_t[bh * Sc + s0];
            }
            if (s1 == c) {
                v1 = __ldcs(reinterpret_cast<const float4*>(q_t + bh * Sc) + tid);
                if (c >= t && c < t + 4)
                    reinterpret_cast<float*>(&v1)[c - t] = k_t[bh * Sc + c];
            } else {
                v1 = __ldcs(reinterpret_cast<const float4*>(base + (long)s1 * Sc) + tid);
                if (c >= t && c < t + 4)
                    reinterpret_cast<float*>(&v1)[c - t] = k_t[bh * Sc + s1];
            }
            __stcs(outp, v0);
            __stcs(outp + (Sc / 4), v1);
        }
    } else {
        // ---------------- q/k/v caches: 2 float4 per thread ----------------
        int base = blk * 512;                        // 512-aligned, never spans caches
        int which = base / N4_CACHE;                 // 0=q,1=k,2=v
        const float4* in = (which == 0) ? qc : (which == 1) ? kc : vc;
        const float4* nv = (which == 0) ? qn : (which == 1) ? kn : vn;

        int shift = (csl >= Sc - 1) ? 1 : 0;
        int c     = (csl < Sc - 1) ? csl : (Sc - 1);

        int r0 = (base - which * N4_CACHE) + tid;
        int r1 = r0 + 256;

        int d40 = r0 & (D4c - 1), sA = (r0 >> 4) & (Sc - 1), bh0 = r0 >> 14;
        int d41 = r1 & (D4c - 1), sB = (r1 >> 4) & (Sc - 1), bh1 = r1 >> 14;

        int ssA = sA + shift; if (ssA > Sc - 1) ssA = Sc - 1;
        int ssB = sB + shift; if (ssB > Sc - 1) ssB = Sc - 1;

        float4 vA = (sA == c) ? nv[bh0 * D4c + d40]
                              : __ldcs(in + (long)(bh0 * Sc + ssA) * D4c + d40);
        float4 vB = (sB == c) ? nv[bh1 * D4c + d41]
                              : __ldcs(in + (long)(bh1 * Sc + ssB) * D4c + d41);

        __stcs(out4 + base + tid, vA);
        __stcs(out4 + base + 256 + tid, vB);
    }
}

extern "C" void kernel_launch(void* const* d_in, const int* in_sizes, int n_in,
                              void* d_out, int out_size)
{
    const float4* qc  = (const float4*)d_in[0];
    const float4* kc  = (const float4*)d_in[1];
    const float4* vc  = (const float4*)d_in[2];
    const float*  ac  = (const float*) d_in[3];
    const float4* qn  = (const float4*)d_in[4];
    const float4* kn  = (const float4*)d_in[5];
    const float4* vn  = (const float4*)d_in[6];
    const float*  qt  = (const float*) d_in[7];
    const float*  kt  = (const float*) d_in[8];
    const int*    csl = (const int*)   d_in[9];

    float4* out4 = (float4*)d_out;

    sliding_cache_fused<<<ATTN_BLOCKS + QKV_BLOCKS, 256>>>(
        qc, kc, vc, ac, qn, kn, vn, qt, kt, csl, out4);
}

// round 15
// speedup vs baseline: 1.1359x; 1.0061x over previous
#include <cuda_runtime.h>

// SlidingAttnScoreCache — one decode step of a sliding cache at capacity.
// B=8, H=8, S=1024, D=64.
//  0 q_cache (B,H,S,D) f32   1 k_cache   2 v_cache
//  3 attn_score_cache (B,H,S,S) f32
//  4 q (B,H,1,D)  5 k  6 v
//  7 q_t (B,H,1,S)  8 k_t (B,H,S,1)  9 current_seq_len (scalar int)
// Output: concat[q_cache', k_cache', v_cache', attn_score_cache'] f32.
//
// Roofline note: ~637 MB pure data movement, 50/50 R/W. Nine structural
// variants all pin at 82-83% DRAM (~6.6 TB/s) — the mixed read/write HBM
// turnaround ceiling on this part. This is the best-measured variant (R4).

#define Bc 8
#define Hc 8
#define Sc 1024
#define Dc 64
#define D4c (Dc / 4)
#define N_CACHE (Bc * Hc * Sc * Dc)      // 4,194,304 floats per qkv cache
#define N4_CACHE (N_CACHE / 4)           // 1,048,576 float4
#define BH (Bc * Hc)
#define ATTN_BLOCKS (BH * Sc / 2)        // 32768 blocks, 2 rows each
#define QKV_BLOCKS (3 * N4_CACHE / 512)  // 6144 blocks, 2 float4/thread

// Assemble out[s, 4t..4t+3] = in[ss, 4t+2..4t+5] from the aligned load A_t,
// using shuffles for the cross-thread pair; lane31 uses ext (predicated 8B
// load); tid==255 clamps col 1024 -> 1023 and sets col 1023 (== c) to k_t[s].
__device__ __forceinline__
float4 shift2_assemble(float4 A, float2 ext, int tid, int lane, float ktv)
{
    float nx = __shfl_down_sync(0xffffffffu, A.x, 1);
    float ny = __shfl_down_sync(0xffffffffu, A.y, 1);
    if (lane == 31) { nx = ext.x; ny = ext.y; }
    float4 v;
    v.x = A.z; v.y = A.w; v.z = nx; v.w = ny;
    if (tid == 255) { v.z = A.w; v.w = ktv; }
    return v;
}

__global__ __launch_bounds__(256)
void sliding_cache_fused(const float4* __restrict__ qc,
                         const float4* __restrict__ kc,
                         const float4* __restrict__ vc,
                         const float*  __restrict__ a_in,
                         const float4* __restrict__ qn,
                         const float4* __restrict__ kn,
                         const float4* __restrict__ vn,
                         const float*  __restrict__ q_t,
                         const float*  __restrict__ k_t,
                         const int*    __restrict__ csl_ptr,
                         float4* __restrict__ out4)
{
    int blk  = blockIdx.x;
    int tid  = threadIdx.x;
    int lane = tid & 31;
    int csl  = *csl_ptr;

    if (blk < ATTN_BLOCKS) {
        // ---------------- attn score cache: rows 2*blk, 2*blk+1 ----------------
        int row0 = blk * 2;
        int s0   = row0 & (Sc - 1);          // even
        int s1   = s0 + 1;
        int bh   = row0 >> 10;
        int t    = tid << 2;
        int shift = (csl >= Sc - 1) ? 2 : 0;
        int c     = (csl < Sc - 1) ? csl : (Sc - 1);

        float4* outp = out4 + (long)(3 * N4_CACHE);
        long o0 = (long)row0 * (Sc / 4) + tid;

        if (shift == 2) {
            // c == S-1; s0 is even so s0 != c; s1 may be c (last pair).
            int ss0 = s0 + 2; if (ss0 > Sc - 1) ss0 = Sc - 1;
            int ss1 = s1 + 2; if (ss1 > Sc - 1) ss1 = Sc - 1;
            const float* ir0 = a_in + (long)(bh * Sc + ss0) * Sc;
            const float* ir1 = a_in + (long)(bh * Sc + ss1) * Sc;

            // batch all loads (2 independent LDG.128 + predicated 8B tails)
            float4 A0 = __ldcs(reinterpret_cast<const float4*>(ir0) + tid);
            float4 A1 = __ldcs(reinterpret_cast<const float4*>(ir1) + tid);
            float2 e0, e1;
            if (lane == 31 && tid != 255) {
                e0 = *reinterpret_cast<const float2*>(ir0 + t + 4);
                e1 = *reinterpret_cast<const float2*>(ir1 + t + 4);
            }
            float kt0 = k_t[bh * Sc + s0];
            float kt1 = k_t[bh * Sc + s1];

            float4 v0 = shift2_assemble(A0, e0, tid, lane, kt0);
            float4 v1 = shift2_assemble(A1, e1, tid, lane, kt1);

            if (s1 == c) {
                // row c <- q_t, column c (tid 255, elem w) <- k_t[c]
                v1 = __ldcs(reinterpret_cast<const float4*>(q_t + bh * Sc) + tid);
                if (c >= t && c < t + 4)
                    reinterpret_cast<float*>(&v1)[c - t] = kt1;
            }
            __stcs(outp + o0, v0);
            __stcs(outp + o0 + (Sc / 4), v1);
        } else {
            // shift == 0: plain row copies with patches
            const float* base = a_in + (long)bh * Sc * Sc;
            float4 v0, v1;
            if (s0 == c) {
                v0 = __ldcs(reinterpret_cast<const float4*>(q_t + bh * Sc) + tid);
                if (c >= t && c < t + 4)
                    reinterpret_cast<float*>(&v0)[c - t] = k_t[bh * Sc + c];
            } else {
                v0 = __ldcs(reinterpret_cast<const float4*>(base + (long)s0 * Sc) + tid);
                if (c >= t && c < t + 4)
                    reinterpret_cast<float*>(&v0)[c - t] = k_t[bh * Sc + s0];
            }
            if (s1 == c) {
                v1 = __ldcs(reinterpret_cast<const float4*>(q_t + bh * Sc) + tid);
                if (c >= t && c < t + 4)
                    reinterpret_cast<float*>(&v1)[c - t] = k_t[bh * Sc + c];
            } else {
                v1 = __ldcs(reinterpret_cast<const float4*>(base + (long)s1 * Sc) + tid);
                if (c >= t && c < t + 4)
                    reinterpret_cast<float*>(&v1)[c - t] = k_t[bh * Sc + s1];
            }
            __stcs(outp + o0, v0);
            __stcs(outp + o0 + (Sc / 4), v1);
        }
    } else {
        // ---------------- q/k/v caches: 2 float4 per thread ----------------
        int base = (blk - ATTN_BLOCKS) * 512;            // 512-aligned, never spans caches
        int which = base / N4_CACHE;                     // 0=q,1=k,2=v
        const float4* in = (which == 0) ? qc : (which == 1) ? kc : vc;
        const float4* nv = (which == 0) ? qn : (which == 1) ? kn : vn;

        int shift = (csl >= Sc - 1) ? 1 : 0;
        int c     = (csl < Sc - 1) ? csl : (Sc - 1);

        int r0 = (base - which * N4_CACHE) + tid;
        int r1 = r0 + 256;

        int d40 = r0 & (D4c - 1), sA = (r0 >> 4) & (Sc - 1), bh0 = r0 >> 14;
        int d41 = r1 & (D4c - 1), sB = (r1 >> 4) & (Sc - 1), bh1 = r1 >> 14;

        int ssA = sA + shift; if (ssA > Sc - 1) ssA = Sc - 1;
        int ssB = sB + shift; if (ssB > Sc - 1) ssB = Sc - 1;

        float4 vA = (sA == c) ? nv[bh0 * D4c + d40]
                              : __ldcs(in + (long)(bh0 * Sc + ssA) * D4c + d40);
        float4 vB = (sB == c) ? nv[bh1 * D4c + d41]
                              : __ldcs(in + (long)(bh1 * Sc + ssB) * D4c + d41);

        __stcs(out4 + base + tid, vA);
        __stcs(out4 + base + 256 + tid, vB);
    }
}

extern "C" void kernel_launch(void* const* d_in, const int* in_sizes, int n_in,
                              void* d_out, int out_size)
{
    const float4* qc  = (const float4*)d_in[0];
    const float4* kc  = (const float4*)d_in[1];
    const float4* vc  = (const float4*)d_in[2];
    const float*  ac  = (const float*) d_in[3];
    const float4* qn  = (const float4*)d_in[4];
    const float4* kn  = (const float4*)d_in[5];
    const float4* vn  = (const float4*)d_in[6];
    const float*  qt  = (const float*) d_in[7];
    const float*  kt  = (const float*) d_in[8];
    const int*    csl = (const int*)   d_in[9];

    float4* out4 = (float4*)d_out;

    sliding_cache_fused<<<ATTN_BLOCKS + QKV_BLOCKS, 256>>>(
        qc, kc, vc, ac, qn, kn, vn, qt, kt, csl, out4);
}